// round 11
// baseline (speedup 1.0000x reference)
#include <cuda_runtime.h>

#define NN 100000
#define EE 1600000
#define EPSI 1e-12f
#define CAP 64                       // padded bucket capacity per dst node

// ---------------- scratch (device globals; no allocation allowed) ----------------
__device__ float4 g_h4[NN * 16];     // h1 (N x 64); later h2b (N x 32)
__device__ float4 g_t4[NN * 8];      // h2pre (N x 32)
__device__ float  g_degO[3 * NN];
__device__ int    g_cur[3 * NN];     // bucket cursors == in-degree counts after fill
__device__ int2   g_csr[3 * NN * CAP];   // (src, __float_as_int(w)) padded buckets by dst

// ---------------- zero: degO + cur ----------------
__global__ void k_zero() {
    int i = blockIdx.x * blockDim.x + threadIdx.x;
    if (i < 3 * NN) { g_degO[i] = 0.f; g_cur[i] = 0; }
}

// ---------------- one-pass build: degO atomic + bucket scatter, 3 graphs ----------------
__global__ void k_fill3(const int* __restrict__ s1, const int* __restrict__ d1, const float* __restrict__ w1,
                        const int* __restrict__ s2, const int* __restrict__ d2, const float* __restrict__ w2,
                        const int* __restrict__ s3, const int* __restrict__ d3, const float* __restrict__ w3) {
    int g = blockIdx.y;
    const int*   src = (g == 0) ? s1 : (g == 1) ? s2 : s3;
    const int*   dst = (g == 0) ? d1 : (g == 1) ? d2 : d3;
    const float* w   = (g == 0) ? w1 : (g == 1) ? w2 : w3;
    int e = blockIdx.x * blockDim.x + threadIdx.x;
    if (e < EE) {
        int s = src[e], d = dst[e];
        float wv = w[e];
        atomicAdd(&g_degO[g * NN + s], wv);
        int pos = atomicAdd(&g_cur[g * NN + d], 1);
        g_csr[(g * NN + d) * CAP + pos] = make_int2(s, __float_as_int(wv));
    }
}

// ---------------- mm1: h1 = x @ W1  (N x 128)@(128 x 64) -> g_h4 ----------------
__global__ void k_mm1(const float* __restrict__ x, const float* __restrict__ W1) {
    __shared__ float ws[128 * 64];   // 32 KB
    __shared__ float xs[32 * 128];   // 16 KB
    int t = threadIdx.x;
    {
        const float4* W14 = (const float4*)W1;
        float4* ws4w = (float4*)ws;
        #pragma unroll
        for (int i = 0; i < 8; i++) ws4w[t + i * 256] = W14[t + i * 256];
    }
    const float4* ws4 = (const float4*)ws;
    int jg = t & 15;
    int r  = t >> 4;
    int row0 = blockIdx.x * 32;      // grid = 3125, exact
    {
        const float4* x4 = (const float4*)x;
        float4* xs4 = (float4*)xs;
        #pragma unroll
        for (int i = 0; i < 4; i++) {
            int idx = t + i * 256;
            xs4[idx] = x4[row0 * 32 + idx];
        }
    }
    __syncthreads();
    float4 a0 = make_float4(0.f, 0.f, 0.f, 0.f);
    float4 a1 = make_float4(0.f, 0.f, 0.f, 0.f);
    #pragma unroll 4
    for (int k = 0; k < 128; k++) {
        float  x0 = xs[r * 128 + k];
        float  x1 = xs[(r + 16) * 128 + k];
        float4 wv = ws4[k * 16 + jg];
        a0.x += x0 * wv.x; a0.y += x0 * wv.y; a0.z += x0 * wv.z; a0.w += x0 * wv.w;
        a1.x += x1 * wv.x; a1.y += x1 * wv.y; a1.z += x1 * wv.z; a1.w += x1 * wv.w;
    }
    g_h4[(row0 + r) * 16 + jg]      = a0;
    g_h4[(row0 + r + 16) * 16 + jg] = a1;
}

// ---------------- fused pull64 (g=0) + mm2: h2pre = (agg1/dw + b1) @ W2 -> g_t4 ------
// 512 threads = 16 warps; warp w owns row blockIdx.x*16 + w.
// Lane = ep*16 + fl: ep in {0,1} edge-parallel, fl in 0..15 feature float4.
__global__ void __launch_bounds__(512) k_pull64mm2(const float* __restrict__ b1,
                                                   const float* __restrict__ W2) {
    __shared__ float hs[16 * 64];    // 4 KB block tile of h1b
    __shared__ float ws[64 * 32];    // 8 KB W2
    int t = threadIdx.x;
    ((float4*)ws)[t] = ((const float4*)W2)[t];   // 512 float4 = 2048 floats
    int w  = t >> 5;
    int ln = t & 31;
    int ep = ln >> 4;                // 0..1
    int fl = ln & 15;                // 0..15
    int row = blockIdx.x * 16 + w;   // exact: 6250*16 = 100000
    int cnt = g_cur[row];
    int base = row * CAP;
    float4 acc = make_float4(0.f, 0.f, 0.f, 0.f);
    float dw = 0.f;
    #pragma unroll 4
    for (int j = ep; j < cnt; j += 2) {
        int2 e = __ldcs(&g_csr[base + j]);
        float n = __int_as_float(e.y) * rsqrtf(fmaxf(__ldg(&g_degO[e.x]), EPSI));
        float4 h = g_h4[e.x * 16 + fl];
        acc.x += h.x * n; acc.y += h.y * n;
        acc.z += h.z * n; acc.w += h.w * n;
        dw += n;
    }
    // reduce across ep (xor 16)
    acc.x += __shfl_xor_sync(0xffffffffu, acc.x, 16);
    acc.y += __shfl_xor_sync(0xffffffffu, acc.y, 16);
    acc.z += __shfl_xor_sync(0xffffffffu, acc.z, 16);
    acc.w += __shfl_xor_sync(0xffffffffu, acc.w, 16);
    dw    += __shfl_xor_sync(0xffffffffu, dw, 16);
    if (ep == 0) {
        float inv = 1.f / fmaxf(dw, EPSI);
        float4 bb = ((const float4*)b1)[fl];
        ((float4*)hs)[w * 16 + fl] = make_float4(acc.x * inv + bb.x, acc.y * inv + bb.y,
                                                 acc.z * inv + bb.z, acc.w * inv + bb.w);
    }
    __syncthreads();
    // mm2: 16x64 @ 64x32 -> 16x32; thread -> (r = t>>5, c = t&31)
    int r = t >> 5, c = t & 31;
    float s = 0.f;
    #pragma unroll
    for (int k = 0; k < 64; k++)
        s += hs[r * 64 + k] * ws[k * 32 + c];
    ((float*)g_t4)[(blockIdx.x * 16 + r) * 32 + c] = s;
}

// ---------------- pull32 layer 2 (g=1): h2b = agg2/dw + b2 : g_t4 -> g_h4 -----------
__global__ void __launch_bounds__(512) k_pull32L2(const float* __restrict__ b2) {
    int t = threadIdx.x;
    int w  = t >> 5;
    int ln = t & 31;
    int ep = ln >> 3;                // 0..3
    int fl = ln & 7;                 // 0..7
    int row = blockIdx.x * 16 + w;
    const float* degO = g_degO + NN;
    int cnt = g_cur[NN + row];
    int base = (NN + row) * CAP;
    float4 acc = make_float4(0.f, 0.f, 0.f, 0.f);
    float dw = 0.f;
    #pragma unroll 4
    for (int j = ep; j < cnt; j += 4) {
        int2 e = __ldcs(&g_csr[base + j]);
        float n = __int_as_float(e.y) * rsqrtf(fmaxf(__ldg(&degO[e.x]), EPSI));
        float4 h = g_t4[e.x * 8 + fl];
        acc.x += h.x * n; acc.y += h.y * n;
        acc.z += h.z * n; acc.w += h.w * n;
        dw += n;
    }
    acc.x += __shfl_xor_sync(0xffffffffu, acc.x, 8);
    acc.y += __shfl_xor_sync(0xffffffffu, acc.y, 8);
    acc.z += __shfl_xor_sync(0xffffffffu, acc.z, 8);
    acc.w += __shfl_xor_sync(0xffffffffu, acc.w, 8);
    dw    += __shfl_xor_sync(0xffffffffu, dw, 8);
    acc.x += __shfl_xor_sync(0xffffffffu, acc.x, 16);
    acc.y += __shfl_xor_sync(0xffffffffu, acc.y, 16);
    acc.z += __shfl_xor_sync(0xffffffffu, acc.z, 16);
    acc.w += __shfl_xor_sync(0xffffffffu, acc.w, 16);
    dw    += __shfl_xor_sync(0xffffffffu, dw, 16);
    if (ep == 0) {
        float inv = 1.f / fmaxf(dw, EPSI);
        float4 bb = ((const float4*)b2)[fl];
        g_h4[row * 8 + fl] = make_float4(acc.x * inv + bb.x, acc.y * inv + bb.y,
                                         acc.z * inv + bb.z, acc.w * inv + bb.w);
    }
}

// ---------------- fused pull32 layer 3 (g=2) + fin3: out = (agg3/dw) @ W3 + b3 ------
__global__ void __launch_bounds__(512) k_pull32fin3(const float* __restrict__ W3,
                                                    const float* __restrict__ b3,
                                                    float* __restrict__ out) {
    __shared__ float hs[16 * 32];    // 2 KB block tile of aggnorm3
    __shared__ float ws[32 * 32];    // 4 KB W3
    int t = threadIdx.x;
    if (t < 256) ((float4*)ws)[t] = ((const float4*)W3)[t];   // 256 float4 = 1024 floats
    int w  = t >> 5;
    int ln = t & 31;
    int ep = ln >> 3;
    int fl = ln & 7;
    int row = blockIdx.x * 16 + w;
    const float* degO = g_degO + 2 * NN;
    int cnt = g_cur[2 * NN + row];
    int base = (2 * NN + row) * CAP;
    float4 acc = make_float4(0.f, 0.f, 0.f, 0.f);
    float dw = 0.f;
    #pragma unroll 4
    for (int j = ep; j < cnt; j += 4) {
        int2 e = __ldcs(&g_csr[base + j]);
        float n = __int_as_float(e.y) * rsqrtf(fmaxf(__ldg(&degO[e.x]), EPSI));
        float4 h = g_h4[e.x * 8 + fl];
        acc.x += h.x * n; acc.y += h.y * n;
        acc.z += h.z * n; acc.w += h.w * n;
        dw += n;
    }
    acc.x += __shfl_xor_sync(0xffffffffu, acc.x, 8);
    acc.y += __shfl_xor_sync(0xffffffffu, acc.y, 8);
    acc.z += __shfl_xor_sync(0xffffffffu, acc.z, 8);
    acc.w += __shfl_xor_sync(0xffffffffu, acc.w, 8);
    dw    += __shfl_xor_sync(0xffffffffu, dw, 8);
    acc.x += __shfl_xor_sync(0xffffffffu, acc.x, 16);
    acc.y += __shfl_xor_sync(0xffffffffu, acc.y, 16);
    acc.z += __shfl_xor_sync(0xffffffffu, acc.z, 16);
    acc.w += __shfl_xor_sync(0xffffffffu, acc.w, 16);
    dw    += __shfl_xor_sync(0xffffffffu, dw, 16);
    if (ep == 0) {
        float inv = 1.f / fmaxf(dw, EPSI);
        ((float4*)hs)[w * 8 + fl] = make_float4(acc.x * inv, acc.y * inv,
                                                acc.z * inv, acc.w * inv);
    }
    __syncthreads();
    // fin3: 16x32 @ 32x32 + b3
    int r = t >> 5, c = t & 31;
    float s = 0.f;
    #pragma unroll
    for (int k = 0; k < 32; k++)
        s += hs[r * 32 + k] * ws[k * 32 + c];
    out[(blockIdx.x * 16 + r) * 32 + c] = s + b3[c];
}

// ---------------- launch ----------------
extern "C" void kernel_launch(void* const* d_in, const int* in_sizes, int n_in,
                              void* d_out, int out_size) {
    const float* x    = (const float*)d_in[0];
    const int*   src1 = (const int*)  d_in[1];
    const int*   dst1 = (const int*)  d_in[2];
    const float* w1   = (const float*)d_in[3];
    const int*   src2 = (const int*)  d_in[4];
    const int*   dst2 = (const int*)  d_in[5];
    const float* w2   = (const float*)d_in[6];
    const int*   src3 = (const int*)  d_in[7];
    const int*   dst3 = (const int*)  d_in[8];
    const float* w3   = (const float*)d_in[9];
    const float* W1   = (const float*)d_in[10];
    const float* b1   = (const float*)d_in[11];
    const float* W2   = (const float*)d_in[12];
    const float* b2   = (const float*)d_in[13];
    const float* W3   = (const float*)d_in[14];
    const float* b3   = (const float*)d_in[15];
    float* out = (float*)d_out;

    const int TB = 256;
    dim3 gE3((EE + TB - 1) / TB, 3);             // 6250 x 3 blocks, 1 edge/thread

    // slots arranged so ncu captures k_pull64mm2 (launch index 3)
    k_mm1<<<NN / 32, 256>>>(x, W1);                      // 0 (independent)
    k_zero<<<(3 * NN + TB - 1) / TB, TB>>>();            // 1
    k_fill3<<<gE3, TB>>>(src1, dst1, w1, src2, dst2, w2, src3, dst3, w3);   // 2
    k_pull64mm2<<<NN / 16, 512>>>(b1, W2);               // 3  <- captured
    k_pull32L2<<<NN / 16, 512>>>(b2);                    // 4
    k_pull32fin3<<<NN / 16, 512>>>(W3, b3, out);         // 5
}

// round 14
// speedup vs baseline: 1.0135x; 1.0135x over previous
#include <cuda_runtime.h>

#define NN 100000
#define EE 1600000
#define EPSI 1e-12f
#define CAP 64                       // padded bucket capacity per dst node

// ---------------- scratch (device globals; no allocation allowed) ----------------
__device__ float4 g_h4[NN * 16];     // h1 (N x 64); later h2b (N x 32)
__device__ float4 g_t4[NN * 8];      // h2pre (N x 32)
__device__ float  g_degO[3 * NN];
__device__ int    g_cur[3 * NN];     // bucket cursors == in-degree counts after fill
__device__ int2   g_csr[3 * NN * CAP];   // (src, __float_as_int(w)) padded buckets by dst

// ---------------- zero: degO + cur ----------------
__global__ void k_zero() {
    int i = blockIdx.x * blockDim.x + threadIdx.x;
    if (i < 3 * NN) { g_degO[i] = 0.f; g_cur[i] = 0; }
}

// ---------------- one-pass build: degO atomic + bucket scatter, 3 graphs ----------------
__global__ void k_fill3(const int* __restrict__ s1, const int* __restrict__ d1, const float* __restrict__ w1,
                        const int* __restrict__ s2, const int* __restrict__ d2, const float* __restrict__ w2,
                        const int* __restrict__ s3, const int* __restrict__ d3, const float* __restrict__ w3) {
    int g = blockIdx.y;
    const int*   src = (g == 0) ? s1 : (g == 1) ? s2 : s3;
    const int*   dst = (g == 0) ? d1 : (g == 1) ? d2 : d3;
    const float* w   = (g == 0) ? w1 : (g == 1) ? w2 : w3;
    int e = blockIdx.x * blockDim.x + threadIdx.x;
    if (e < EE) {
        int s = src[e], d = dst[e];
        float wv = w[e];
        atomicAdd(&g_degO[g * NN + s], wv);
        int pos = atomicAdd(&g_cur[g * NN + d], 1);
        g_csr[(g * NN + d) * CAP + pos] = make_int2(s, __float_as_int(wv));
    }
}

// ---------------- mm1: h1 = x @ W1  (N x 128)@(128 x 64) -> g_h4 ----------------
__global__ void k_mm1(const float* __restrict__ x, const float* __restrict__ W1) {
    __shared__ float ws[128 * 64];   // 32 KB
    __shared__ float xs[32 * 128];   // 16 KB
    int t = threadIdx.x;
    {
        const float4* W14 = (const float4*)W1;
        float4* ws4w = (float4*)ws;
        #pragma unroll
        for (int i = 0; i < 8; i++) ws4w[t + i * 256] = W14[t + i * 256];
    }
    const float4* ws4 = (const float4*)ws;
    int jg = t & 15;
    int r  = t >> 4;
    int row0 = blockIdx.x * 32;      // grid = 3125, exact
    {
        const float4* x4 = (const float4*)x;
        float4* xs4 = (float4*)xs;
        #pragma unroll
        for (int i = 0; i < 4; i++) {
            int idx = t + i * 256;
            xs4[idx] = x4[row0 * 32 + idx];
        }
    }
    __syncthreads();
    float4 a0 = make_float4(0.f, 0.f, 0.f, 0.f);
    float4 a1 = make_float4(0.f, 0.f, 0.f, 0.f);
    #pragma unroll 4
    for (int k = 0; k < 128; k++) {
        float  x0 = xs[r * 128 + k];
        float  x1 = xs[(r + 16) * 128 + k];
        float4 wv = ws4[k * 16 + jg];
        a0.x += x0 * wv.x; a0.y += x0 * wv.y; a0.z += x0 * wv.z; a0.w += x0 * wv.w;
        a1.x += x1 * wv.x; a1.y += x1 * wv.y; a1.z += x1 * wv.z; a1.w += x1 * wv.w;
    }
    g_h4[(row0 + r) * 16 + jg]      = a0;
    g_h4[(row0 + r + 16) * 16 + jg] = a1;
}

// ---------------- fused pull64 (g=0) + mm2: h2pre = (agg1/dw + b1) @ W2 -> g_t4 ------
// 512 threads = 16 warps; warp w owns row blockIdx.x*16 + w.
// Chunked: lane ln loads edge chunk+ln coalesced, computes n; shfl distributes.
// Trip count is warp-uniform: trips = ceil(kmax/2); shuffles unconditional.
__global__ void __launch_bounds__(512) k_pull64mm2(const float* __restrict__ b1,
                                                   const float* __restrict__ W2) {
    __shared__ float hs[16 * 64];    // 4 KB block tile of h1b
    __shared__ float ws[64 * 32];    // 8 KB W2
    int t = threadIdx.x;
    ((float4*)ws)[t] = ((const float4*)W2)[t];   // 512 float4 = 2048 floats
    int w  = t >> 5;
    int ln = t & 31;
    int ep = ln >> 4;                // 0..1
    int fl = ln & 15;                // 0..15
    int row = blockIdx.x * 16 + w;   // exact: 6250*16 = 100000
    int cnt = g_cur[row];
    int base = row * CAP;
    float4 acc = make_float4(0.f, 0.f, 0.f, 0.f);
    float dw = 0.f;
    for (int chunk = 0; chunk < cnt; chunk += 32) {
        int idx = chunk + ln;
        int2 e = make_int2(0, 0);
        if (idx < cnt) e = __ldcs(&g_csr[base + idx]);
        float n_ln = __int_as_float(e.y) * rsqrtf(fmaxf(__ldg(&g_degO[e.x]), EPSI));
        int kmax = min(32, cnt - chunk);   // warp-uniform
        int trips = (kmax + 1) >> 1;       // warp-uniform
        #pragma unroll 4
        for (int kk = 0; kk < trips; kk++) {
            int k = kk * 2 + ep;           // <= 31 always
            int   s = __shfl_sync(0xffffffffu, e.x, k);
            float n = __shfl_sync(0xffffffffu, n_ln, k);
            if (k < kmax) {
                float4 h = g_h4[s * 16 + fl];
                acc.x += h.x * n; acc.y += h.y * n;
                acc.z += h.z * n; acc.w += h.w * n;
                dw += n;
            }
        }
    }
    // reduce across ep (xor 16)
    acc.x += __shfl_xor_sync(0xffffffffu, acc.x, 16);
    acc.y += __shfl_xor_sync(0xffffffffu, acc.y, 16);
    acc.z += __shfl_xor_sync(0xffffffffu, acc.z, 16);
    acc.w += __shfl_xor_sync(0xffffffffu, acc.w, 16);
    dw    += __shfl_xor_sync(0xffffffffu, dw, 16);
    if (ep == 0) {
        float inv = 1.f / fmaxf(dw, EPSI);
        float4 bb = ((const float4*)b1)[fl];
        ((float4*)hs)[w * 16 + fl] = make_float4(acc.x * inv + bb.x, acc.y * inv + bb.y,
                                                 acc.z * inv + bb.z, acc.w * inv + bb.w);
    }
    __syncthreads();
    // mm2: 16x64 @ 64x32 -> 16x32; thread -> (r = t>>5, c = t&31)
    int r = t >> 5, c = t & 31;
    float s = 0.f;
    #pragma unroll
    for (int k = 0; k < 64; k++)
        s += hs[r * 64 + k] * ws[k * 32 + c];
    ((float*)g_t4)[(blockIdx.x * 16 + r) * 32 + c] = s;
}

// ---------------- pull32 layer 2 (g=1): h2b = agg2/dw + b2 : g_t4 -> g_h4 -----------
// ep = ln>>3 (0..3), fl = ln&7; trips = ceil(kmax/4), shuffles unconditional.
__global__ void __launch_bounds__(512) k_pull32L2(const float* __restrict__ b2) {
    int t = threadIdx.x;
    int w  = t >> 5;
    int ln = t & 31;
    int ep = ln >> 3;                // 0..3
    int fl = ln & 7;                 // 0..7
    int row = blockIdx.x * 16 + w;
    const float* degO = g_degO + NN;
    int cnt = g_cur[NN + row];
    int base = (NN + row) * CAP;
    float4 acc = make_float4(0.f, 0.f, 0.f, 0.f);
    float dw = 0.f;
    for (int chunk = 0; chunk < cnt; chunk += 32) {
        int idx = chunk + ln;
        int2 e = make_int2(0, 0);
        if (idx < cnt) e = __ldcs(&g_csr[base + idx]);
        float n_ln = __int_as_float(e.y) * rsqrtf(fmaxf(__ldg(&degO[e.x]), EPSI));
        int kmax = min(32, cnt - chunk);
        int trips = (kmax + 3) >> 2;
        #pragma unroll 4
        for (int kk = 0; kk < trips; kk++) {
            int k = kk * 4 + ep;           // <= 31 always
            int   s = __shfl_sync(0xffffffffu, e.x, k);
            float n = __shfl_sync(0xffffffffu, n_ln, k);
            if (k < kmax) {
                float4 h = g_t4[s * 8 + fl];
                acc.x += h.x * n; acc.y += h.y * n;
                acc.z += h.z * n; acc.w += h.w * n;
                dw += n;
            }
        }
    }
    acc.x += __shfl_xor_sync(0xffffffffu, acc.x, 8);
    acc.y += __shfl_xor_sync(0xffffffffu, acc.y, 8);
    acc.z += __shfl_xor_sync(0xffffffffu, acc.z, 8);
    acc.w += __shfl_xor_sync(0xffffffffu, acc.w, 8);
    dw    += __shfl_xor_sync(0xffffffffu, dw, 8);
    acc.x += __shfl_xor_sync(0xffffffffu, acc.x, 16);
    acc.y += __shfl_xor_sync(0xffffffffu, acc.y, 16);
    acc.z += __shfl_xor_sync(0xffffffffu, acc.z, 16);
    acc.w += __shfl_xor_sync(0xffffffffu, acc.w, 16);
    dw    += __shfl_xor_sync(0xffffffffu, dw, 16);
    if (ep == 0) {
        float inv = 1.f / fmaxf(dw, EPSI);
        float4 bb = ((const float4*)b2)[fl];
        g_h4[row * 8 + fl] = make_float4(acc.x * inv + bb.x, acc.y * inv + bb.y,
                                         acc.z * inv + bb.z, acc.w * inv + bb.w);
    }
}

// ---------------- fused pull32 layer 3 (g=2) + fin3: out = (agg3/dw) @ W3 + b3 ------
__global__ void __launch_bounds__(512) k_pull32fin3(const float* __restrict__ W3,
                                                    const float* __restrict__ b3,
                                                    float* __restrict__ out) {
    __shared__ float hs[16 * 32];    // 2 KB block tile of aggnorm3
    __shared__ float ws[32 * 32];    // 4 KB W3
    int t = threadIdx.x;
    if (t < 256) ((float4*)ws)[t] = ((const float4*)W3)[t];   // 256 float4 = 1024 floats
    int w  = t >> 5;
    int ln = t & 31;
    int ep = ln >> 3;
    int fl = ln & 7;
    int row = blockIdx.x * 16 + w;
    const float* degO = g_degO + 2 * NN;
    int cnt = g_cur[2 * NN + row];
    int base = (2 * NN + row) * CAP;
    float4 acc = make_float4(0.f, 0.f, 0.f, 0.f);
    float dw = 0.f;
    for (int chunk = 0; chunk < cnt; chunk += 32) {
        int idx = chunk + ln;
        int2 e = make_int2(0, 0);
        if (idx < cnt) e = __ldcs(&g_csr[base + idx]);
        float n_ln = __int_as_float(e.y) * rsqrtf(fmaxf(__ldg(&degO[e.x]), EPSI));
        int kmax = min(32, cnt - chunk);
        int trips = (kmax + 3) >> 2;
        #pragma unroll 4
        for (int kk = 0; kk < trips; kk++) {
            int k = kk * 4 + ep;           // <= 31 always
            int   s = __shfl_sync(0xffffffffu, e.x, k);
            float n = __shfl_sync(0xffffffffu, n_ln, k);
            if (k < kmax) {
                float4 h = g_h4[s * 8 + fl];
                acc.x += h.x * n; acc.y += h.y * n;
                acc.z += h.z * n; acc.w += h.w * n;
                dw += n;
            }
        }
    }
    acc.x += __shfl_xor_sync(0xffffffffu, acc.x, 8);
    acc.y += __shfl_xor_sync(0xffffffffu, acc.y, 8);
    acc.z += __shfl_xor_sync(0xffffffffu, acc.z, 8);
    acc.w += __shfl_xor_sync(0xffffffffu, acc.w, 8);
    dw    += __shfl_xor_sync(0xffffffffu, dw, 8);
    acc.x += __shfl_xor_sync(0xffffffffu, acc.x, 16);
    acc.y += __shfl_xor_sync(0xffffffffu, acc.y, 16);
    acc.z += __shfl_xor_sync(0xffffffffu, acc.z, 16);
    acc.w += __shfl_xor_sync(0xffffffffu, acc.w, 16);
    dw    += __shfl_xor_sync(0xffffffffu, dw, 16);
    if (ep == 0) {
        float inv = 1.f / fmaxf(dw, EPSI);
        ((float4*)hs)[w * 8 + fl] = make_float4(acc.x * inv, acc.y * inv,
                                                acc.z * inv, acc.w * inv);
    }
    __syncthreads();
    // fin3: 16x32 @ 32x32 + b3
    int r = t >> 5, c = t & 31;
    float s = 0.f;
    #pragma unroll
    for (int k = 0; k < 32; k++)
        s += hs[r * 32 + k] * ws[k * 32 + c];
    out[(blockIdx.x * 16 + r) * 32 + c] = s + b3[c];
}

// ---------------- launch ----------------
extern "C" void kernel_launch(void* const* d_in, const int* in_sizes, int n_in,
                              void* d_out, int out_size) {
    const float* x    = (const float*)d_in[0];
    const int*   src1 = (const int*)  d_in[1];
    const int*   dst1 = (const int*)  d_in[2];
    const float* w1   = (const float*)d_in[3];
    const int*   src2 = (const int*)  d_in[4];
    const int*   dst2 = (const int*)  d_in[5];
    const float* w2   = (const float*)d_in[6];
    const int*   src3 = (const int*)  d_in[7];
    const int*   dst3 = (const int*)  d_in[8];
    const float* w3   = (const float*)d_in[9];
    const float* W1   = (const float*)d_in[10];
    const float* b1   = (const float*)d_in[11];
    const float* W2   = (const float*)d_in[12];
    const float* b2   = (const float*)d_in[13];
    const float* W3   = (const float*)d_in[14];
    const float* b3   = (const float*)d_in[15];
    float* out = (float*)d_out;

    const int TB = 256;
    dim3 gE3((EE + TB - 1) / TB, 3);             // 6250 x 3 blocks, 1 edge/thread

    // slots arranged so ncu captures k_pull64mm2 (launch index 3)
    k_mm1<<<NN / 32, 256>>>(x, W1);                      // 0 (independent)
    k_zero<<<(3 * NN + TB - 1) / TB, TB>>>();            // 1
    k_fill3<<<gE3, TB>>>(src1, dst1, w1, src2, dst2, w2, src3, dst3, w3);   // 2
    k_pull64mm2<<<NN / 16, 512>>>(b1, W2);               // 3  <- captured
    k_pull32L2<<<NN / 16, 512>>>(b2);                    // 4
    k_pull32fin3<<<NN / 16, 512>>>(W3, b3, out);         // 5
}